// round 11
// baseline (speedup 1.0000x reference)
#include <cuda_runtime.h>
#include <stdint.h>

// Best-known skeleton (R10: 78.5us) + batched independent probe loads.
// Query keys -> exact open-addressing table (4MB, L2-resident); 10M data
// triples stream through; per thread, 4 keys' probe loads issued back-to-back
// (MLP=4) before any dependent branch. Inputs are int32 (JAX x64 disabled);
// triple key (h*15000+r)*15000+t wraps in int32 == uint32 arithmetic.
#define QT_LOG2 19
#define QT_SIZE (1u << QT_LOG2)
#define QT_MASK (QT_SIZE - 1u)
#define EMPTY64 0xFFFFFFFFFFFFFFFFull
#define FOUND_BIT (1ull << 32)
#define N_ENT 15000u
#define MAX_Q (1 << 17)

__device__ unsigned long long g_qtable[QT_SIZE];   // 2^19 * 8B = 4MB
__device__ int g_qslot[MAX_Q];

__device__ __forceinline__ uint32_t make_key(uint32_t h, uint32_t r, uint32_t t) {
    return (h * N_ENT + r) * N_ENT + t;   // wraps mod 2^32 == int32 reference
}

// Fibonacci multiply-shift: IMAD + SHF; top bits well-mixed.
__device__ __forceinline__ uint32_t hash_slot(uint32_t key) {
    return (key * 2654435769u) >> (32 - QT_LOG2);
}

__device__ __forceinline__ unsigned long long ld_cg64(const unsigned long long* p) {
    unsigned long long v;
    asm volatile("ld.global.cg.u64 %0, [%1];" : "=l"(v) : "l"(p));
    return v;
}
__device__ __forceinline__ void st_cg64(unsigned long long* p, unsigned long long v) {
    asm volatile("st.global.cg.u64 [%0], %1;" :: "l"(p), "l"(v));
}

// ---- Pass A: clear table ----
__global__ void clear_kernel() {
    uint32_t tid = blockIdx.x * blockDim.x + threadIdx.x;
    uint32_t stride = gridDim.x * blockDim.x;
    ulonglong2* p = reinterpret_cast<ulonglong2*>(g_qtable);
    ulonglong2 v; v.x = EMPTY64; v.y = EMPTY64;
    for (uint32_t i = tid; i < QT_SIZE / 2; i += stride) p[i] = v;
}

// ---- Pass B: insert query keys, record slot ----
__global__ void insert_queries_kernel(const int* __restrict__ heads,
                                      const int* __restrict__ rels,
                                      const int* __restrict__ tails, int q) {
    int i = blockIdx.x * blockDim.x + threadIdx.x;
    if (i >= q) return;
    uint32_t key = make_key((uint32_t)heads[i], (uint32_t)rels[i], (uint32_t)tails[i]);
    uint32_t slot = hash_slot(key);
    while (true) {
        unsigned long long v = ld_cg64(&g_qtable[slot]);
        if (v != EMPTY64 && (uint32_t)v == key) break;      // dup
        if (v == EMPTY64) {
            unsigned long long prev =
                atomicCAS(&g_qtable[slot], EMPTY64, (unsigned long long)key);
            if (prev == EMPTY64 || (uint32_t)prev == key) break;
        }
        slot = (slot + 1) & QT_MASK;
    }
    g_qslot[i] = (int)slot;
}

// ---- Pass C: stream data, batched probe loads ----
// Finish one key given its already-loaded first slot value. Rare fallback loop.
__device__ __forceinline__ void finish_probe(uint32_t key, uint32_t slot,
                                             unsigned long long v) {
    while (true) {
        if (v == EMPTY64) return;                   // definite miss (common)
        if ((uint32_t)v == key) {
            if (!(v & FOUND_BIT))
                st_cg64(&g_qtable[slot], (unsigned long long)key | FOUND_BIT);
            return;
        }
        slot = (slot + 1) & QT_MASK;
        v = ld_cg64(&g_qtable[slot]);
    }
}

__global__ void mark_kernel(const int* __restrict__ data, int n4, int n) {
    int i = blockIdx.x * blockDim.x + threadIdx.x;
    if (i < n4) {
        const int4* d0 = reinterpret_cast<const int4*>(data);
        const int4* d1 = reinterpret_cast<const int4*>(data + n);
        const int4* d2 = reinterpret_cast<const int4*>(data + 2 * n);
        int4 h = d0[i], r = d1[i], t = d2[i];
        uint32_t k0 = make_key((uint32_t)h.x, (uint32_t)r.x, (uint32_t)t.x);
        uint32_t k1 = make_key((uint32_t)h.y, (uint32_t)r.y, (uint32_t)t.y);
        uint32_t k2 = make_key((uint32_t)h.z, (uint32_t)r.z, (uint32_t)t.z);
        uint32_t k3 = make_key((uint32_t)h.w, (uint32_t)r.w, (uint32_t)t.w);
        uint32_t s0 = hash_slot(k0), s1 = hash_slot(k1);
        uint32_t s2 = hash_slot(k2), s3 = hash_slot(k3);
        // 4 independent loads in flight before any dependent branch
        unsigned long long v0 = ld_cg64(&g_qtable[s0]);
        unsigned long long v1 = ld_cg64(&g_qtable[s1]);
        unsigned long long v2 = ld_cg64(&g_qtable[s2]);
        unsigned long long v3 = ld_cg64(&g_qtable[s3]);
        finish_probe(k0, s0, v0);
        finish_probe(k1, s1, v1);
        finish_probe(k2, s2, v2);
        finish_probe(k3, s3, v3);
    }
    // tail elements (n not divisible by 4)
    int tail_start = n4 * 4;
    int ti = tail_start + i;
    if (i < n - tail_start) {
        uint32_t k = make_key((uint32_t)data[ti], (uint32_t)data[n + ti],
                              (uint32_t)data[2 * n + ti]);
        uint32_t s = hash_slot(k);
        finish_probe(k, s, ld_cg64(&g_qtable[s]));
    }
}

// ---- Pass D: resolve via recorded slot ----
__global__ void resolve_kernel(float* __restrict__ out, int q) {
    int i = blockIdx.x * blockDim.x + threadIdx.x;
    if (i >= q) return;
    unsigned long long v = ld_cg64(&g_qtable[g_qslot[i]]);
    out[i] = (v & FOUND_BIT) ? 5.0f : -5.0f;
}

extern "C" void kernel_launch(void* const* d_in, const int* in_sizes, int n_in,
                              void* d_out, int out_size) {
    const int* heads = (const int*)d_in[0];
    const int* rels  = (const int*)d_in[1];
    const int* tails = (const int*)d_in[2];
    const int* data  = (const int*)d_in[3];
    float* out = (float*)d_out;

    const int q = in_sizes[0];
    const int n = in_sizes[3] / 3;
    const int n4 = n >> 2;
    const int threads = 256;

    // A: clear 4MB qtable
    clear_kernel<<<148 * 4, threads>>>();
    // B: insert query keys + record slots
    insert_queries_kernel<<<(q + threads - 1) / threads, threads>>>(heads, rels, tails, q);
    // C: one thread per 4 keys, batched independent probes
    mark_kernel<<<(n4 + threads - 1) / threads, threads>>>(data, n4, n);
    // D: write +/-5 per query from recorded slot
    resolve_kernel<<<(q + threads - 1) / threads, threads>>>(out, q);
}

// round 13
// speedup vs baseline: 1.0344x; 1.0344x over previous
#include <cuda_runtime.h>
#include <stdint.h>

// R10 skeleton (best: 78.5us) + L2-residency protection:
//  - data stream read with ld.global.cs (evict-first) so the 120MB/call
//    stream does not evict the 4MB hash table from L2
//  - found flags moved to a 64KB bitmap (L1-resident for resolve)
// Inputs are int32 (JAX x64 disabled); triple key (h*15000+r)*15000+t wraps
// in int32 == uint32 arithmetic.
#define QT_LOG2 19
#define QT_SIZE (1u << QT_LOG2)
#define QT_MASK (QT_SIZE - 1u)
#define EMPTY64 0xFFFFFFFFFFFFFFFFull
#define N_ENT 15000u
#define MAX_Q (1 << 17)

__device__ unsigned long long g_qtable[QT_SIZE];      // 4MB key table
__device__ uint32_t g_found[QT_SIZE / 32];            // 64KB found bitmap
__device__ int g_qslot[MAX_Q];

__device__ __forceinline__ uint32_t make_key(uint32_t h, uint32_t r, uint32_t t) {
    return (h * N_ENT + r) * N_ENT + t;   // wraps mod 2^32 == int32 reference
}

// Fibonacci multiply-shift: IMAD + SHF; top bits well-mixed.
__device__ __forceinline__ uint32_t hash_slot(uint32_t key) {
    return (key * 2654435769u) >> (32 - QT_LOG2);
}

__device__ __forceinline__ unsigned long long ld_cg64(const unsigned long long* p) {
    unsigned long long v;
    asm volatile("ld.global.cg.u64 %0, [%1];" : "=l"(v) : "l"(p));
    return v;
}
// evict-first streaming load for the one-shot data pass
__device__ __forceinline__ int4 ld_cs128(const int4* p) {
    int4 v;
    asm volatile("ld.global.cs.v4.s32 {%0,%1,%2,%3}, [%4];"
                 : "=r"(v.x), "=r"(v.y), "=r"(v.z), "=r"(v.w) : "l"(p));
    return v;
}
__device__ __forceinline__ int ld_cs32(const int* p) {
    int v;
    asm volatile("ld.global.cs.s32 %0, [%1];" : "=r"(v) : "l"(p));
    return v;
}

// ---- Pass A: clear table + bitmap ----
__global__ void clear_kernel() {
    uint32_t tid = blockIdx.x * blockDim.x + threadIdx.x;
    uint32_t stride = gridDim.x * blockDim.x;
    ulonglong2* p = reinterpret_cast<ulonglong2*>(g_qtable);
    ulonglong2 v; v.x = EMPTY64; v.y = EMPTY64;
    for (uint32_t i = tid; i < QT_SIZE / 2; i += stride) p[i] = v;
    for (uint32_t i = tid; i < QT_SIZE / 32; i += stride) g_found[i] = 0u;
}

// ---- Pass B: insert query keys, record slot ----
__global__ void insert_queries_kernel(const int* __restrict__ heads,
                                      const int* __restrict__ rels,
                                      const int* __restrict__ tails, int q) {
    int i = blockIdx.x * blockDim.x + threadIdx.x;
    if (i >= q) return;
    uint32_t key = make_key((uint32_t)heads[i], (uint32_t)rels[i], (uint32_t)tails[i]);
    uint32_t slot = hash_slot(key);
    while (true) {
        unsigned long long v = ld_cg64(&g_qtable[slot]);
        if (v != EMPTY64 && (uint32_t)v == key) break;      // dup
        if (v == EMPTY64) {
            unsigned long long prev =
                atomicCAS(&g_qtable[slot], EMPTY64, (unsigned long long)key);
            if (prev == EMPTY64 || (uint32_t)prev == key) break;
        }
        slot = (slot + 1) & QT_MASK;
    }
    g_qslot[i] = (int)slot;
}

// ---- Pass C: stream data (evict-first), probe table (L2-resident) ----
__device__ __forceinline__ void probe_mark(uint32_t key) {
    uint32_t slot = hash_slot(key);
    unsigned long long v = ld_cg64(&g_qtable[slot]);
    if (v == EMPTY64) return;                 // expected path: 1 load, done
    while (true) {
        if ((uint32_t)v == key) {
            // ~hundreds of true hits total across the whole pass
            atomicOr(&g_found[slot >> 5], 1u << (slot & 31));
            return;
        }
        slot = (slot + 1) & QT_MASK;
        v = ld_cg64(&g_qtable[slot]);
        if (v == EMPTY64) return;
    }
}

__global__ void mark_kernel(const int* __restrict__ data, int n4, int n) {
    int i = blockIdx.x * blockDim.x + threadIdx.x;
    if (i < n4) {
        const int4* d0 = reinterpret_cast<const int4*>(data);
        const int4* d1 = reinterpret_cast<const int4*>(data + n);
        const int4* d2 = reinterpret_cast<const int4*>(data + 2 * n);
        int4 h = ld_cs128(&d0[i]);
        int4 r = ld_cs128(&d1[i]);
        int4 t = ld_cs128(&d2[i]);
        probe_mark(make_key((uint32_t)h.x, (uint32_t)r.x, (uint32_t)t.x));
        probe_mark(make_key((uint32_t)h.y, (uint32_t)r.y, (uint32_t)t.y));
        probe_mark(make_key((uint32_t)h.z, (uint32_t)r.z, (uint32_t)t.z));
        probe_mark(make_key((uint32_t)h.w, (uint32_t)r.w, (uint32_t)t.w));
    }
    // tail elements (n not divisible by 4)
    int tail_start = n4 * 4;
    int ti = tail_start + i;
    if (i < n - tail_start) {
        probe_mark(make_key((uint32_t)ld_cs32(&data[ti]),
                            (uint32_t)ld_cs32(&data[n + ti]),
                            (uint32_t)ld_cs32(&data[2 * n + ti])));
    }
}

// ---- Pass D: resolve via recorded slot + L1-resident bitmap ----
__global__ void resolve_kernel(float* __restrict__ out, int q) {
    int i = blockIdx.x * blockDim.x + threadIdx.x;
    if (i >= q) return;
    uint32_t slot = (uint32_t)g_qslot[i];
    uint32_t w = g_found[slot >> 5];          // 64KB region -> L1 hits
    out[i] = ((w >> (slot & 31)) & 1u) ? 5.0f : -5.0f;
}

extern "C" void kernel_launch(void* const* d_in, const int* in_sizes, int n_in,
                              void* d_out, int out_size) {
    const int* heads = (const int*)d_in[0];
    const int* rels  = (const int*)d_in[1];
    const int* tails = (const int*)d_in[2];
    const int* data  = (const int*)d_in[3];
    float* out = (float*)d_out;

    const int q = in_sizes[0];
    const int n = in_sizes[3] / 3;
    const int n4 = n >> 2;
    const int threads = 256;

    // A: clear 4MB qtable + 64KB bitmap
    clear_kernel<<<148 * 4, threads>>>();
    // B: insert query keys + record slots
    insert_queries_kernel<<<(q + threads - 1) / threads, threads>>>(heads, rels, tails, q);
    // C: one thread per 4 keys; streaming data reads, L2-resident probes
    mark_kernel<<<(n4 + threads - 1) / threads, threads>>>(data, n4, n);
    // D: write +/-5 per query from slot + bitmap
    resolve_kernel<<<(q + threads - 1) / threads, threads>>>(out, q);
}